// round 15
// baseline (speedup 1.0000x reference)
#include <cuda_runtime.h>
#include <cuda_fp16.h>
#include <math.h>
#include <stdint.h>

// Problem constants
#define B_   256
#define S_   128
#define P_   100
#define N_   500
#define E_   256
#define H_   4
#define HD_  64
#define L_   2
#define F_   1024
#define T_   (B_ * S_)      // 32768 tokens
#define NT_  (P_ + N_)      // 600 targets
#define NTH_ (NT_ / 2)      // 300 pairs per sample

// ---------------------------------------------------------------------------
// Scratch (device globals — no allocation allowed). Activations in fp16.
// ---------------------------------------------------------------------------
__device__ __half g_x   [(size_t)T_ * E_];
__device__ __half g_qkv [(size_t)T_ * 3 * E_];
__device__ __half g_attn[(size_t)T_ * E_];
__device__ __half g_tmp [(size_t)T_ * E_];
__device__ __half g_ff  [(size_t)T_ * F_];
__device__ float  g_out [(size_t)B_ * 3 * E_];
__device__ __half g_wh  [1572864];            // fp16 weights (3MB)

// half-element offsets into g_wh
#define WR_QKV 0
#define WR_AO  393216
#define WR_FF1 524288
#define WR_FF2 1048576

// ---------------------------------------------------------------------------
// helpers
// ---------------------------------------------------------------------------
__device__ __forceinline__ void cp16(void* sdst, const void* gsrc) {
    uint32_t s = (uint32_t)__cvta_generic_to_shared(sdst);
    asm volatile("cp.async.cg.shared.global [%0], [%1], 16;\n" :: "r"(s), "l"(gsrc));
}
__device__ __forceinline__ void cp_commit() {
    asm volatile("cp.async.commit_group;\n");
}
template<int NWait>
__device__ __forceinline__ void cp_wait() {
    asm volatile("cp.async.wait_group %0;\n" :: "n"(NWait));
}
__device__ __forceinline__ uint32_t f22h2(float a, float b) {
    __half2 h = __floats2half2_rn(a, b);
    return *(uint32_t*)&h;
}
__device__ __forceinline__ float2 h22f2(uint32_t u) {
    return __half22float2(*(__half2*)&u);
}
#define MMA_F16(d, a, b)                                                      \
    asm volatile(                                                             \
        "mma.sync.aligned.m16n8k16.row.col.f32.f16.f16.f32 "                  \
        "{%0,%1,%2,%3}, {%4,%5,%6,%7}, {%8,%9}, {%0,%1,%2,%3};"               \
        : "+f"(d[0]), "+f"(d[1]), "+f"(d[2]), "+f"(d[3])                      \
        : "r"(a[0]), "r"(a[1]), "r"(a[2]), "r"(a[3]), "r"(b[0]), "r"(b[1]))

// ---------------------------------------------------------------------------
// Weight conversion fp32 -> fp16 (once per launch)
// ---------------------------------------------------------------------------
__global__ void conv_w_kernel(const float4* __restrict__ qkvw,
                              const float4* __restrict__ aow,
                              const float4* __restrict__ f1w,
                              const float4* __restrict__ f2w,
                              uint32_t* __restrict__ dst) {
    const int i = blockIdx.x * blockDim.x + threadIdx.x;
    if (i >= 393216) return;
    float4 v;
    int o = i;
    if (o < 98304)                  v = qkvw[o];
    else if ((o -= 98304) < 32768)  v = aow[o];
    else if ((o -= 32768) < 131072) v = f1w[o];
    else                            v = f2w[o - 131072];
    dst[2 * i]     = f22h2(v.x, v.y);
    dst[2 * i + 1] = f22h2(v.z, v.w);
}

// ---------------------------------------------------------------------------
// Embedding gather: fp32 emb -> fp16 x. Thread handles 8 halves.
// ---------------------------------------------------------------------------
__global__ void gather_kernel(const int* __restrict__ attr,
                              const float* __restrict__ emb,
                              __half* __restrict__ x) {
    int i = blockIdx.x * blockDim.x + threadIdx.x;
    if (i < T_ * (E_ / 8)) {
        int t  = i >> 5;
        int e8 = i & 31;
        const float4* src = (const float4*)(emb + (size_t)attr[t] * E_) + e8 * 2;
        float4 v0 = src[0], v1 = src[1];
        uint4 o;
        o.x = f22h2(v0.x, v0.y); o.y = f22h2(v0.z, v0.w);
        o.z = f22h2(v1.x, v1.y); o.w = f22h2(v1.z, v1.w);
        *(uint4*)(x + (size_t)t * E_ + e8 * 8) = o;
    }
}

// ---------------------------------------------------------------------------
// FP16 tensor-core GEMM: C = A @ B^T + bias (opt ReLU, opt +resid), fp32
// accum. Block 128x128, BK=32 halves (two m16n8k16 steps per stage -> one
// syncthreads per 32 K), 8 warps of 64x32, 3-stage cp.async, 2 CTAs/SM.
// Smem rows: 32 halves = 16 u32 + 4 pad (LDW=20, banks 20r mod 32 =
// {0,20,8,28,16,4,24,12} -> conflict-free fragments). Requires K%32==0.
// ---------------------------------------------------------------------------
#define LDW    20
#define TSZ    (128 * LDW)     // u32 per matrix per stage
#define STAGES 3

template<bool RELU, bool RES>
__global__ __launch_bounds__(256, 2)
void hgemm(const __half* __restrict__ A, const __half* __restrict__ Bm,
           const float* __restrict__ bias, const __half* __restrict__ resid,
           __half* __restrict__ C, int M, int N, int K) {
    extern __shared__ uint32_t smh[];
    uint32_t* As = smh;
    uint32_t* Bs = smh + STAGES * TSZ;

    const int bm   = blockIdx.y * 128;
    const int bn   = blockIdx.x * 128;
    const int t    = threadIdx.x;
    const int lane = t & 31;
    const int wid  = t >> 5;
    const int wm   = (wid & 1) * 64;
    const int wn   = (wid >> 1) * 32;
    const int g    = lane >> 2;
    const int tg   = lane & 3;

    const int lrow = t >> 1;            // 0..127
    const int lk   = (t & 1);           // which 16-half chunk pair
    const __half* Ap = A  + (size_t)(bm + lrow) * K + lk * 16;
    const __half* Bp = Bm + (size_t)(bn + lrow) * K + lk * 16;

    float acc[4][4][4];
#pragma unroll
    for (int i = 0; i < 4; i++)
#pragma unroll
        for (int j = 0; j < 4; j++)
#pragma unroll
            for (int r = 0; r < 4; r++) acc[i][j][r] = 0.f;

    const int nk = K >> 5;
#pragma unroll
    for (int s = 0; s < STAGES - 1; s++) {
        const int k0 = s << 5;
        cp16(&As[s * TSZ + lrow * LDW + lk * 8],     Ap + k0);
        cp16(&As[s * TSZ + lrow * LDW + lk * 8 + 4], Ap + k0 + 8);
        cp16(&Bs[s * TSZ + lrow * LDW + lk * 8],     Bp + k0);
        cp16(&Bs[s * TSZ + lrow * LDW + lk * 8 + 4], Bp + k0 + 8);
        cp_commit();
    }

    int cur = 0;
    for (int kt = 0; kt < nk; kt++) {
        if (kt < nk - 1) cp_wait<STAGES - 2>(); else cp_wait<0>();
        __syncthreads();

        const uint32_t* Ac = As + cur * TSZ;
        const uint32_t* Bc = Bs + cur * TSZ;
#pragma unroll
        for (int ks = 0; ks < 2; ks++) {
            const int k2 = ks * 8;
            uint32_t af[4][4], bf[4][2];
#pragma unroll
            for (int mf = 0; mf < 4; mf++) {
                const int row = wm + mf * 16 + g;
                af[mf][0] = Ac[row * LDW + k2 + tg];
                af[mf][1] = Ac[(row + 8) * LDW + k2 + tg];
                af[mf][2] = Ac[row * LDW + k2 + tg + 4];
                af[mf][3] = Ac[(row + 8) * LDW + k2 + tg + 4];
            }
#pragma unroll
            for (int nf = 0; nf < 4; nf++) {
                const int col = wn + nf * 8 + g;
                bf[nf][0] = Bc[col * LDW + k2 + tg];
                bf[nf][1] = Bc[col * LDW + k2 + tg + 4];
            }
#pragma unroll
            for (int mf = 0; mf < 4; mf++)
#pragma unroll
                for (int nf = 0; nf < 4; nf++) MMA_F16(acc[mf][nf], af[mf], bf[nf]);
        }

        const int pf = kt + STAGES - 1;
        if (pf < nk) {
            const int ps = pf % STAGES;
            const int k0 = pf << 5;
            cp16(&As[ps * TSZ + lrow * LDW + lk * 8],     Ap + k0);
            cp16(&As[ps * TSZ + lrow * LDW + lk * 8 + 4], Ap + k0 + 8);
            cp16(&Bs[ps * TSZ + lrow * LDW + lk * 8],     Bp + k0);
            cp16(&Bs[ps * TSZ + lrow * LDW + lk * 8 + 4], Bp + k0 + 8);
            cp_commit();
        }
        cur = (cur + 1 == STAGES) ? 0 : cur + 1;
    }

    // epilogue: bias (+ReLU / +residual), half2 stores
#pragma unroll
    for (int nf = 0; nf < 4; nf++) {
        const int col = bn + wn + nf * 8 + 2 * tg;
        const float b0v = bias[col], b1v = bias[col + 1];
#pragma unroll
        for (int mf = 0; mf < 4; mf++) {
            const int row = bm + wm + mf * 16 + g;
            float v0 = acc[mf][nf][0] + b0v;
            float v1 = acc[mf][nf][1] + b1v;
            float v2 = acc[mf][nf][2] + b0v;
            float v3 = acc[mf][nf][3] + b1v;
            if (RES) {
                float2 r0 = h22f2(*(const uint32_t*)(resid + (size_t)row * N + col));
                float2 r1 = h22f2(*(const uint32_t*)(resid + (size_t)(row + 8) * N + col));
                v0 += r0.x; v1 += r0.y; v2 += r1.x; v3 += r1.y;
            }
            if (RELU) {
                v0 = fmaxf(v0, 0.f); v1 = fmaxf(v1, 0.f);
                v2 = fmaxf(v2, 0.f); v3 = fmaxf(v3, 0.f);
            }
            *(uint32_t*)(C + (size_t)row * N + col)       = f22h2(v0, v1);
            *(uint32_t*)(C + (size_t)(row + 8) * N + col) = f22h2(v2, v3);
        }
    }
}

// ---------------------------------------------------------------------------
// FP16 tensor-core attention (R14-proven): one block per (b,h), 512 threads.
// ---------------------------------------------------------------------------
#define QLD2 36
#define PLD3 68
#define VT_OFF 0
#define Q_OFF  (64 * PLD3)                 // 4352
#define K_OFF  (Q_OFF + 128 * QLD2)        // 8960
#define P_OFF  Q_OFF                       // overlays Q+K
#define PART_OFF (K_OFF + 128 * QLD2)      // 13568 (float units)
#define RSUM_OFF (PART_OFF + 512)          // 14080
#define ATTN_SMEMU (RSUM_OFF + 128)        // 14208 u32 = 56832 B

__global__ __launch_bounds__(512)
void attn_kernel(const __half* __restrict__ qkv,
                 const int* __restrict__ lens,
                 __half* __restrict__ out) {
    const int bh = blockIdx.x;
    const int b  = bh / H_;
    const int h  = bh % H_;
    extern __shared__ uint32_t smu[];
    float*  smf = (float*)smu;
    __half* smx = (__half*)smu;

    const int t    = threadIdx.x;
    const int lane = t & 31;
    const int wid  = t >> 5;
    const int g    = lane >> 2;
    const int tg   = lane & 3;
    const int len  = lens[b];

    for (int i4 = t; i4 < S_ * 8; i4 += 512) {
        const int s  = i4 >> 3;
        const int d8 = i4 & 7;
        const float4* base =
            (const float4*)(qkv + (size_t)(b * S_ + s) * (3 * E_) + h * HD_);
        float4 qv = base[d8];
        float4 kv = base[32 + d8];
        float4 vv = base[64 + d8];
        *(float4*)&smu[Q_OFF + s * QLD2 + d8 * 4] = qv;
        *(float4*)&smu[K_OFF + s * QLD2 + d8 * 4] = kv;
        const __half* vh = (const __half*)&vv;
        const int d0 = d8 * 8;
#pragma unroll
        for (int j = 0; j < 8; j++)
            smx[(d0 + j) * (PLD3 * 2) + s] = vh[j];
    }
    __syncthreads();

    // ---- phase 1: warp tile 32(q) x 32(k), 4x4 warp grid, 4 k16 steps ----
    const int wm = (wid & 3) * 32;
    const int wn = (wid >> 2) * 32;
    float acc[2][4][4];
#pragma unroll
    for (int i = 0; i < 2; i++)
#pragma unroll
        for (int j = 0; j < 4; j++)
#pragma unroll
            for (int r = 0; r < 4; r++) acc[i][j][r] = 0.f;

#pragma unroll
    for (int ks = 0; ks < 4; ks++) {
        const int k2 = ks * 8;
        uint32_t af[2][4], bf[4][2];
#pragma unroll
        for (int mf = 0; mf < 2; mf++) {
            const int row = wm + mf * 16 + g;
            af[mf][0] = smu[Q_OFF + row * QLD2 + k2 + tg];
            af[mf][1] = smu[Q_OFF + (row + 8) * QLD2 + k2 + tg];
            af[mf][2] = smu[Q_OFF + row * QLD2 + k2 + tg + 4];
            af[mf][3] = smu[Q_OFF + (row + 8) * QLD2 + k2 + tg + 4];
        }
#pragma unroll
        for (int nf = 0; nf < 4; nf++) {
            const int col = wn + nf * 8 + g;
            bf[nf][0] = smu[K_OFF + col * QLD2 + k2 + tg];
            bf[nf][1] = smu[K_OFF + col * QLD2 + k2 + tg + 4];
        }
#pragma unroll
        for (int mf = 0; mf < 2; mf++)
#pragma unroll
            for (int nf = 0; nf < 4; nf++) MMA_F16(acc[mf][nf], af[mf], bf[nf]);
    }

    // exp + row partial sums
    float rs[2][2];
#pragma unroll
    for (int mf = 0; mf < 2; mf++) { rs[mf][0] = 0.f; rs[mf][1] = 0.f; }
#pragma unroll
    for (int mf = 0; mf < 2; mf++) {
#pragma unroll
        for (int nf = 0; nf < 4; nf++) {
            const int c0 = wn + nf * 8 + 2 * tg;
            const int c1 = c0 + 1;
            float* d = acc[mf][nf];
            d[0] = (c0 < len) ? __expf(d[0] * 0.125f) : 0.f;
            d[1] = (c1 < len) ? __expf(d[1] * 0.125f) : 0.f;
            d[2] = (c0 < len) ? __expf(d[2] * 0.125f) : 0.f;
            d[3] = (c1 < len) ? __expf(d[3] * 0.125f) : 0.f;
            rs[mf][0] += d[0] + d[1];
            rs[mf][1] += d[2] + d[3];
        }
#pragma unroll
        for (int o = 1; o < 4; o <<= 1) {
            rs[mf][0] += __shfl_xor_sync(0xffffffffu, rs[mf][0], o);
            rs[mf][1] += __shfl_xor_sync(0xffffffffu, rs[mf][1], o);
        }
    }
    __syncthreads();   // Q/K reads done -> overlay P

    const int nidx = wid >> 2;
#pragma unroll
    for (int mf = 0; mf < 2; mf++) {
        const int r0 = wm + mf * 16 + g;
        const int r1 = r0 + 8;
#pragma unroll
        for (int nf = 0; nf < 4; nf++) {
            const int c2 = (wn >> 1) + nf * 4 + tg;   // half2 index of col c0
            const float* d = acc[mf][nf];
            smu[P_OFF + r0 * PLD3 + c2] = f22h2(d[0], d[1]);
            smu[P_OFF + r1 * PLD3 + c2] = f22h2(d[2], d[3]);
        }
        if (tg == 0) {
            smf[PART_OFF + r0 * 4 + nidx] = rs[mf][0];
            smf[PART_OFF + r1 * 4 + nidx] = rs[mf][1];
        }
    }
    __syncthreads();

    if (t < 128) {
        const float s = smf[PART_OFF + t * 4] + smf[PART_OFF + t * 4 + 1] +
                        smf[PART_OFF + t * 4 + 2] + smf[PART_OFF + t * 4 + 3];
        smf[RSUM_OFF + t] = 1.f / s;
    }
    __syncthreads();

    // ---- phase 2: warp tile 16(q) x 32(d), 8x2 warp grid, 8 k16 steps ----
    const int wm2 = (wid & 7) * 16;
    const int wn2 = (wid >> 3) * 32;
    float acc2[4][4];
#pragma unroll
    for (int j = 0; j < 4; j++)
#pragma unroll
        for (int r = 0; r < 4; r++) acc2[j][r] = 0.f;

#pragma unroll
    for (int ks = 0; ks < 8; ks++) {
        const int k2 = ks * 8;
        uint32_t af[4], bf[4][2];
        {
            const int row = wm2 + g;
            af[0] = smu[P_OFF + row * PLD3 + k2 + tg];
            af[1] = smu[P_OFF + (row + 8) * PLD3 + k2 + tg];
            af[2] = smu[P_OFF + row * PLD3 + k2 + tg + 4];
            af[3] = smu[P_OFF + (row + 8) * PLD3 + k2 + tg + 4];
        }
#pragma unroll
        for (int nf = 0; nf < 4; nf++) {
            const int col = wn2 + nf * 8 + g;
            bf[nf][0] = smu[VT_OFF + col * PLD3 + k2 + tg];
            bf[nf][1] = smu[VT_OFF + col * PLD3 + k2 + tg + 4];
        }
#pragma unroll
        for (int nf = 0; nf < 4; nf++) MMA_F16(acc2[nf], af, bf[nf]);
    }

    // normalize + store (half2)
    {
        const int r0 = wm2 + g;
        const int r1 = r0 + 8;
        const float i0 = smf[RSUM_OFF + r0];
        const float i1 = smf[RSUM_OFF + r1];
#pragma unroll
        for (int nf = 0; nf < 4; nf++) {
            const int c = wn2 + nf * 8 + 2 * tg;
            const float* d = acc2[nf];
            *(uint32_t*)(out + (size_t)(b * S_ + r0) * E_ + h * HD_ + c) =
                f22h2(d[0] * i0, d[1] * i0);
            *(uint32_t*)(out + (size_t)(b * S_ + r1) * E_ + h * HD_ + c) =
                f22h2(d[2] * i1, d[3] * i1);
        }
    }
}

// ---------------------------------------------------------------------------
// LayerNorm (single input; residual already fused into GEMM epilogue):
// warp per token, fp16 in/out, fp32 math.
// ---------------------------------------------------------------------------
__global__ __launch_bounds__(256)
void ln_kernel(const __half* __restrict__ in,
               const float* __restrict__ sc, const float* __restrict__ bi,
               __half* __restrict__ out) {
    const int tok  = blockIdx.x * 8 + (threadIdx.x >> 5);
    const int lane = threadIdx.x & 31;

    uint4 xv = ((const uint4*)(in + (size_t)tok * E_))[lane];
    float2 v[4];
    v[0] = h22f2(xv.x); v[1] = h22f2(xv.y);
    v[2] = h22f2(xv.z); v[3] = h22f2(xv.w);

    float s = 0.f;
#pragma unroll
    for (int i = 0; i < 4; i++) s += v[i].x + v[i].y;
#pragma unroll
    for (int o = 16; o; o >>= 1) s += __shfl_xor_sync(0xffffffffu, s, o);
    const float m = s * (1.f / E_);

    float q = 0.f;
#pragma unroll
    for (int i = 0; i < 4; i++) {
        q += (v[i].x - m) * (v[i].x - m) + (v[i].y - m) * (v[i].y - m);
    }
#pragma unroll
    for (int o = 16; o; o >>= 1) q += __shfl_xor_sync(0xffffffffu, q, o);
    const float rstd = rsqrtf(q * (1.f / E_) + 1e-5f);

    const float4 s0 = ((const float4*)sc)[lane * 2];
    const float4 s1 = ((const float4*)sc)[lane * 2 + 1];
    const float4 b0 = ((const float4*)bi)[lane * 2];
    const float4 b1 = ((const float4*)bi)[lane * 2 + 1];
    uint4 o;
    o.x = f22h2((v[0].x - m) * rstd * s0.x + b0.x,
                (v[0].y - m) * rstd * s0.y + b0.y);
    o.y = f22h2((v[1].x - m) * rstd * s0.z + b0.z,
                (v[1].y - m) * rstd * s0.w + b0.w);
    o.z = f22h2((v[2].x - m) * rstd * s1.x + b1.x,
                (v[2].y - m) * rstd * s1.y + b1.y);
    o.w = f22h2((v[3].x - m) * rstd * s1.z + b1.z,
                (v[3].y - m) * rstd * s1.w + b1.w);
    ((uint4*)(out + (size_t)tok * E_))[lane] = o;
}

// ---------------------------------------------------------------------------
// Weighted pool + concat (+ sigmoid gate); x fp16, outv fp32
// ---------------------------------------------------------------------------
__global__ __launch_bounds__(256)
void pool_kernel(const __half* __restrict__ x, const float* __restrict__ attr_tf,
                 const int* __restrict__ lens, const int* __restrict__ lens_user,
                 const float* __restrict__ feat, const float* __restrict__ fW,
                 const float* __restrict__ fb,
                 const int* __restrict__ user_ids, const int* __restrict__ item_ids,
                 const float* __restrict__ user_emb, const float* __restrict__ item_emb,
                 float* __restrict__ out) {
    const int b = blockIdx.x;
    const int e = threadIdx.x;
    __shared__ float w[S_];
    __shared__ float wu_s;
    if (e == 0) {
        float z = fb[0];
#pragma unroll
        for (int i = 0; i < 13; i++) z += feat[b * 13 + i] * fW[i];
        wu_s = 1.f / (1.f + expf(-z));
    }
    __syncthreads();
    if (e < S_) {
        const int s = e;
        float wgt = 0.f;
        if (s < lens[b]) {
            const float g = (s < lens_user[b]) ? wu_s : (1.f - wu_s);
            wgt = attr_tf[b * S_ + s] * g;
        }
        w[s] = wgt;
    }
    __syncthreads();
    float acc = 0.f;
    const __half* xb = x + (size_t)b * S_ * E_ + e;
    for (int s = 0; s < S_; s++) acc += w[s] * __half2float(xb[(size_t)s * E_]);
    out[(size_t)b * 3 * E_ + E_ + e]     = acc;
    out[(size_t)b * 3 * E_ + e]          = user_emb[(size_t)user_ids[b] * E_ + e];
    out[(size_t)b * 3 * E_ + 2 * E_ + e] = item_emb[(size_t)item_ids[b] * E_ + e];
}

// ---------------------------------------------------------------------------
// Scoring head: one warp per PAIR of targets (j, j+300); fp32 throughout
// ---------------------------------------------------------------------------
__global__ __launch_bounds__(256)
void logits_kernel(const float* __restrict__ outv, const float* __restrict__ out_emb,
                   const int* __restrict__ pos_t, const int* __restrict__ pos_l,
                   const int* __restrict__ neg_t, const int* __restrict__ neg_l,
                   float* __restrict__ dout) {
    const int gw   = (int)((blockIdx.x * blockDim.x + threadIdx.x) >> 5);
    const int lane = threadIdx.x & 31;
    if (gw >= B_ * NTH_) return;
    const int b  = gw / NTH_;
    const int j1 = gw % NTH_;
    const int j2 = j1 + NTH_;

    const int pl = pos_l[b];
    const int nl = neg_l[b];

    int tgt1; float valid1, posf1;
    if (j1 < P_) {
        tgt1 = pos_t[b * P_ + j1]; valid1 = (j1 < pl) ? 1.f : 0.f; posf1 = 1.f;
    } else {
        const int jn = j1 - P_;
        tgt1 = neg_t[b * N_ + jn]; valid1 = (jn < nl) ? 1.f : 0.f; posf1 = 0.f;
    }
    int tgt2; float valid2, posf2;
    {
        const int jn = j2 - P_;
        tgt2 = neg_t[b * N_ + jn]; valid2 = (jn < nl) ? 1.f : 0.f; posf2 = 0.f;
    }

    const float4* ovs = (const float4*)(outv + (size_t)b * (3 * E_));
    const float4* e1  = (const float4*)(out_emb + (size_t)tgt1 * (3 * E_));
    const float4* e2  = (const float4*)(out_emb + (size_t)tgt2 * (3 * E_));
    float a1 = 0.f, a2 = 0.f;
#pragma unroll
    for (int i = 0; i < 6; i++) {
        const int k4 = lane + i * 32;
        const float4 c  = ovs[k4];
        const float4 r1 = e1[k4];
        const float4 r2 = e2[k4];
        a1 += r1.x * c.x + r1.y * c.y + r1.z * c.z + r1.w * c.w;
        a2 += r2.x * c.x + r2.y * c.y + r2.z * c.z + r2.w * c.w;
    }
#pragma unroll
    for (int o = 16; o; o >>= 1) {
        a1 += __shfl_xor_sync(0xffffffffu, a1, o);
        a2 += __shfl_xor_sync(0xffffffffu, a2, o);
    }
    if (lane == 0) {
        const int idx1 = b * NT_ + j1;
        const int idx2 = b * NT_ + j2;
        dout[idx1]                = a1;
        dout[B_ * NT_ + idx1]     = valid1;
        dout[2 * B_ * NT_ + idx1] = posf1 * valid1;
        dout[idx2]                = a2;
        dout[B_ * NT_ + idx2]     = valid2;
        dout[2 * B_ * NT_ + idx2] = posf2 * valid2;
    }
}

// ---------------------------------------------------------------------------
// Launch
// ---------------------------------------------------------------------------
extern "C" void kernel_launch(void* const* d_in, const int* in_sizes, int n_in,
                              void* d_out, int out_size) {
    const int*   attr           = (const int*)  d_in[0];
    const float* attr_tf        = (const float*)d_in[2];
    const float* attr_feat      = (const float*)d_in[3];
    const int*   attr_lens      = (const int*)  d_in[4];
    const int*   attr_lens_user = (const int*)  d_in[5];
    const int*   user_ids       = (const int*)  d_in[7];
    const int*   item_ids       = (const int*)  d_in[8];
    const int*   pos_targets    = (const int*)  d_in[9];
    const int*   pos_lens       = (const int*)  d_in[10];
    const int*   neg_targets    = (const int*)  d_in[11];
    const int*   neg_lens       = (const int*)  d_in[12];
    const float* attr_emb       = (const float*)d_in[13];
    const float* user_emb       = (const float*)d_in[14];
    const float* item_emb       = (const float*)d_in[15];
    const float* out_emb        = (const float*)d_in[16];
    const float* fw_W           = (const float*)d_in[17];
    const float* fw_b           = (const float*)d_in[18];
    const float* qkv_w          = (const float*)d_in[19];
    const float* qkv_b          = (const float*)d_in[20];
    const float* attn_out_w     = (const float*)d_in[21];
    const float* attn_out_b     = (const float*)d_in[22];
    const float* ln1_s          = (const float*)d_in[23];
    const float* ln1_b          = (const float*)d_in[24];
    const float* ff1_w          = (const float*)d_in[25];
    const float* ff1_b          = (const float*)d_in[26];
    const float* ff2_w          = (const float*)d_in[27];
    const float* ff2_b          = (const float*)d_in[28];
    const float* ln2_s          = (const float*)d_in[29];
    const float* ln2_b          = (const float*)d_in[30];

    __half *x, *qkv, *attn, *tmp, *ff, *wh;
    float *outv;
    cudaGetSymbolAddress((void**)&x,    g_x);
    cudaGetSymbolAddress((void**)&qkv,  g_qkv);
    cudaGetSymbolAddress((void**)&attn, g_attn);
    cudaGetSymbolAddress((void**)&tmp,  g_tmp);
    cudaGetSymbolAddress((void**)&ff,   g_ff);
    cudaGetSymbolAddress((void**)&outv, g_out);
    cudaGetSymbolAddress((void**)&wh,   g_wh);

    const int gemm_smem = STAGES * 2 * TSZ * (int)sizeof(uint32_t);   // 61440
    cudaFuncSetAttribute(hgemm<false, false>,
                         cudaFuncAttributeMaxDynamicSharedMemorySize, gemm_smem);
    cudaFuncSetAttribute(hgemm<true, false>,
                         cudaFuncAttributeMaxDynamicSharedMemorySize, gemm_smem);
    cudaFuncSetAttribute(hgemm<false, true>,
                         cudaFuncAttributeMaxDynamicSharedMemorySize, gemm_smem);
    const int attn_smem = ATTN_SMEMU * (int)sizeof(uint32_t);         // 56832
    cudaFuncSetAttribute(attn_kernel, cudaFuncAttributeMaxDynamicSharedMemorySize,
                         attn_smem);

    conv_w_kernel<<<1536, 256>>>((const float4*)qkv_w, (const float4*)attn_out_w,
                                 (const float4*)ff1_w, (const float4*)ff2_w,
                                 (uint32_t*)wh);
    gather_kernel<<<(T_ * E_ / 8 + 255) / 256, 256>>>(attr, attr_emb, x);

    for (int l = 0; l < L_; l++) {
        const __half* lqkv_w = wh + WR_QKV + (size_t)l * 3 * E_ * E_;
        const __half* lao_w  = wh + WR_AO  + (size_t)l * E_ * E_;
        const __half* lf1_w  = wh + WR_FF1 + (size_t)l * F_ * E_;
        const __half* lf2_w  = wh + WR_FF2 + (size_t)l * E_ * F_;
        const float* lqkv_b = qkv_b      + (size_t)l * 3 * E_;
        const float* lao_b  = attn_out_b + (size_t)l * E_;
        const float* l1s    = ln1_s + (size_t)l * E_;
        const float* l1b    = ln1_b + (size_t)l * E_;
        const float* lf1_b  = ff1_b + (size_t)l * F_;
        const float* lf2_b  = ff2_b + (size_t)l * E_;
        const float* l2s    = ln2_s + (size_t)l * E_;
        const float* l2b    = ln2_b + (size_t)l * E_;

        hgemm<false, false><<<dim3(3 * E_ / 128, T_ / 128), 256, gemm_smem>>>(
            x, lqkv_w, lqkv_b, nullptr, qkv, T_, 3 * E_, E_);
        attn_kernel<<<B_ * H_, 512, attn_smem>>>(qkv, attr_lens, attn);
        // tmp = x + attn @ Wo^T + bo  (residual fused)
        hgemm<false, true><<<dim3(E_ / 128, T_ / 128), 256, gemm_smem>>>(
            attn, lao_w, lao_b, x, tmp, T_, E_, E_);
        ln_kernel<<<T_ / 8, 256>>>(tmp, l1s, l1b, x);
        hgemm<true, false><<<dim3(F_ / 128, T_ / 128), 256, gemm_smem>>>(
            x, lf1_w, lf1_b, nullptr, ff, T_, F_, E_);
        // tmp = x + ff @ W2^T + b2  (residual fused)
        hgemm<false, true><<<dim3(E_ / 128, T_ / 128), 256, gemm_smem>>>(
            ff, lf2_w, lf2_b, x, tmp, T_, E_, F_);
        ln_kernel<<<T_ / 8, 256>>>(tmp, l2s, l2b, x);
    }

    pool_kernel<<<B_, 256>>>(x, attr_tf, attr_lens, attr_lens_user,
                             attr_feat, fw_W, fw_b,
                             user_ids, item_ids, user_emb, item_emb, outv);

    const int nwarps = B_ * NTH_;                      // 76800
    logits_kernel<<<(nwarps * 32 + 255) / 256, 256>>>(
        outv, out_emb, pos_targets, pos_lens, neg_targets, neg_lens,
        (float*)d_out);
}

// round 16
// speedup vs baseline: 1.0169x; 1.0169x over previous
#include <cuda_runtime.h>
#include <cuda_fp16.h>
#include <math.h>
#include <stdint.h>

// Problem constants
#define B_   256
#define S_   128
#define P_   100
#define N_   500
#define E_   256
#define H_   4
#define HD_  64
#define L_   2
#define F_   1024
#define T_   (B_ * S_)      // 32768 tokens
#define NT_  (P_ + N_)      // 600 targets
#define NTH_ (NT_ / 2)      // 300 pairs per sample

// ---------------------------------------------------------------------------
// Scratch (device globals — no allocation allowed). Activations in fp16.
// ---------------------------------------------------------------------------
__device__ __half g_x   [(size_t)T_ * E_];
__device__ __half g_qkv [(size_t)T_ * 3 * E_];
__device__ __half g_attn[(size_t)T_ * E_];
__device__ __half g_tmp [(size_t)T_ * E_];
__device__ __half g_ff  [(size_t)T_ * F_];
__device__ float  g_out [(size_t)B_ * 3 * E_];
__device__ __half g_wh  [1572864];            // fp16 weights (3MB)

// half-element offsets into g_wh
#define WR_QKV 0
#define WR_AO  393216
#define WR_FF1 524288
#define WR_FF2 1048576

// ---------------------------------------------------------------------------
// helpers
// ---------------------------------------------------------------------------
__device__ __forceinline__ void cp16(void* sdst, const void* gsrc) {
    uint32_t s = (uint32_t)__cvta_generic_to_shared(sdst);
    asm volatile("cp.async.cg.shared.global [%0], [%1], 16;\n" :: "r"(s), "l"(gsrc));
}
__device__ __forceinline__ void cp_commit() {
    asm volatile("cp.async.commit_group;\n");
}
template<int NWait>
__device__ __forceinline__ void cp_wait() {
    asm volatile("cp.async.wait_group %0;\n" :: "n"(NWait));
}
__device__ __forceinline__ uint32_t f22h2(float a, float b) {
    __half2 h = __floats2half2_rn(a, b);
    return *(uint32_t*)&h;
}
__device__ __forceinline__ float2 h22f2(uint32_t u) {
    return __half22float2(*(__half2*)&u);
}
#define MMA_F16(d, a, b)                                                      \
    asm volatile(                                                             \
        "mma.sync.aligned.m16n8k16.row.col.f32.f16.f16.f32 "                  \
        "{%0,%1,%2,%3}, {%4,%5,%6,%7}, {%8,%9}, {%0,%1,%2,%3};"               \
        : "+f"(d[0]), "+f"(d[1]), "+f"(d[2]), "+f"(d[3])                      \
        : "r"(a[0]), "r"(a[1]), "r"(a[2]), "r"(a[3]), "r"(b[0]), "r"(b[1]))

// ---------------------------------------------------------------------------
// Weight conversion fp32 -> fp16 (once per launch)
// ---------------------------------------------------------------------------
__global__ void conv_w_kernel(const float4* __restrict__ qkvw,
                              const float4* __restrict__ aow,
                              const float4* __restrict__ f1w,
                              const float4* __restrict__ f2w,
                              uint32_t* __restrict__ dst) {
    const int i = blockIdx.x * blockDim.x + threadIdx.x;
    if (i >= 393216) return;
    float4 v;
    int o = i;
    if (o < 98304)                  v = qkvw[o];
    else if ((o -= 98304) < 32768)  v = aow[o];
    else if ((o -= 32768) < 131072) v = f1w[o];
    else                            v = f2w[o - 131072];
    dst[2 * i]     = f22h2(v.x, v.y);
    dst[2 * i + 1] = f22h2(v.z, v.w);
}

// ---------------------------------------------------------------------------
// Embedding gather: fp32 emb -> fp16 x. Thread handles 8 halves.
// ---------------------------------------------------------------------------
__global__ void gather_kernel(const int* __restrict__ attr,
                              const float* __restrict__ emb,
                              __half* __restrict__ x) {
    int i = blockIdx.x * blockDim.x + threadIdx.x;
    if (i < T_ * (E_ / 8)) {
        int t  = i >> 5;
        int e8 = i & 31;
        const float4* src = (const float4*)(emb + (size_t)attr[t] * E_) + e8 * 2;
        float4 v0 = src[0], v1 = src[1];
        uint4 o;
        o.x = f22h2(v0.x, v0.y); o.y = f22h2(v0.z, v0.w);
        o.z = f22h2(v1.x, v1.y); o.w = f22h2(v1.z, v1.w);
        *(uint4*)(x + (size_t)t * E_ + e8 * 8) = o;
    }
}

// ---------------------------------------------------------------------------
// FP16 tensor-core GEMM: C = A @ B^T + bias (opt ReLU), fp32 accum.
// Block 128x128, BK=32 halves (two m16n8k16 steps per stage -> one
// syncthreads per 32 K), 8 warps of 64x32, 3-stage cp.async, 2 CTAs/SM.
// Smem rows: 32 halves = 16 u32 + 4 pad (LDW=20, banks 20r mod 32 =
// {0,20,8,28,16,4,24,12} -> conflict-free fragments). Requires K%32==0.
// ---------------------------------------------------------------------------
#define LDW    20
#define TSZ    (128 * LDW)     // u32 per matrix per stage
#define STAGES 3

template<bool RELU>
__global__ __launch_bounds__(256, 2)
void hgemm(const __half* __restrict__ A, const __half* __restrict__ Bm,
           const float* __restrict__ bias, __half* __restrict__ C,
           int M, int N, int K) {
    extern __shared__ uint32_t smh[];
    uint32_t* As = smh;
    uint32_t* Bs = smh + STAGES * TSZ;

    const int bm   = blockIdx.y * 128;
    const int bn   = blockIdx.x * 128;
    const int t    = threadIdx.x;
    const int lane = t & 31;
    const int wid  = t >> 5;
    const int wm   = (wid & 1) * 64;
    const int wn   = (wid >> 1) * 32;
    const int g    = lane >> 2;
    const int tg   = lane & 3;

    const int lrow = t >> 1;            // 0..127
    const int lk   = (t & 1);           // which 16-half chunk
    const __half* Ap = A  + (size_t)(bm + lrow) * K + lk * 16;
    const __half* Bp = Bm + (size_t)(bn + lrow) * K + lk * 16;

    float acc[4][4][4];
#pragma unroll
    for (int i = 0; i < 4; i++)
#pragma unroll
        for (int j = 0; j < 4; j++)
#pragma unroll
            for (int r = 0; r < 4; r++) acc[i][j][r] = 0.f;

    const int nk = K >> 5;
#pragma unroll
    for (int s = 0; s < STAGES - 1; s++) {
        const int k0 = s << 5;
        cp16(&As[s * TSZ + lrow * LDW + lk * 8],     Ap + k0);
        cp16(&As[s * TSZ + lrow * LDW + lk * 8 + 4], Ap + k0 + 8);
        cp16(&Bs[s * TSZ + lrow * LDW + lk * 8],     Bp + k0);
        cp16(&Bs[s * TSZ + lrow * LDW + lk * 8 + 4], Bp + k0 + 8);
        cp_commit();
    }

    int cur = 0;
    for (int kt = 0; kt < nk; kt++) {
        if (kt < nk - 1) cp_wait<STAGES - 2>(); else cp_wait<0>();
        __syncthreads();

        const uint32_t* Ac = As + cur * TSZ;
        const uint32_t* Bc = Bs + cur * TSZ;
#pragma unroll
        for (int ks = 0; ks < 2; ks++) {
            const int k2 = ks * 8;
            uint32_t af[4][4], bf[4][2];
#pragma unroll
            for (int mf = 0; mf < 4; mf++) {
                const int row = wm + mf * 16 + g;
                af[mf][0] = Ac[row * LDW + k2 + tg];
                af[mf][1] = Ac[(row + 8) * LDW + k2 + tg];
                af[mf][2] = Ac[row * LDW + k2 + tg + 4];
                af[mf][3] = Ac[(row + 8) * LDW + k2 + tg + 4];
            }
#pragma unroll
            for (int nf = 0; nf < 4; nf++) {
                const int col = wn + nf * 8 + g;
                bf[nf][0] = Bc[col * LDW + k2 + tg];
                bf[nf][1] = Bc[col * LDW + k2 + tg + 4];
            }
#pragma unroll
            for (int mf = 0; mf < 4; mf++)
#pragma unroll
                for (int nf = 0; nf < 4; nf++) MMA_F16(acc[mf][nf], af[mf], bf[nf]);
        }

        const int pf = kt + STAGES - 1;
        if (pf < nk) {
            const int ps = pf % STAGES;
            const int k0 = pf << 5;
            cp16(&As[ps * TSZ + lrow * LDW + lk * 8],     Ap + k0);
            cp16(&As[ps * TSZ + lrow * LDW + lk * 8 + 4], Ap + k0 + 8);
            cp16(&Bs[ps * TSZ + lrow * LDW + lk * 8],     Bp + k0);
            cp16(&Bs[ps * TSZ + lrow * LDW + lk * 8 + 4], Bp + k0 + 8);
            cp_commit();
        }
        cur = (cur + 1 == STAGES) ? 0 : cur + 1;
    }

    // epilogue: bias (+ReLU), half2 stores
#pragma unroll
    for (int nf = 0; nf < 4; nf++) {
        const int col = bn + wn + nf * 8 + 2 * tg;
        const float b0v = bias[col], b1v = bias[col + 1];
#pragma unroll
        for (int mf = 0; mf < 4; mf++) {
            const int row = bm + wm + mf * 16 + g;
            float v0 = acc[mf][nf][0] + b0v;
            float v1 = acc[mf][nf][1] + b1v;
            float v2 = acc[mf][nf][2] + b0v;
            float v3 = acc[mf][nf][3] + b1v;
            if (RELU) {
                v0 = fmaxf(v0, 0.f); v1 = fmaxf(v1, 0.f);
                v2 = fmaxf(v2, 0.f); v3 = fmaxf(v3, 0.f);
            }
            *(uint32_t*)(C + (size_t)row * N + col)       = f22h2(v0, v1);
            *(uint32_t*)(C + (size_t)(row + 8) * N + col) = f22h2(v2, v3);
        }
    }
}

// ---------------------------------------------------------------------------
// FP16 tensor-core attention (R14-proven): one block per (b,h), 512 threads.
// ---------------------------------------------------------------------------
#define QLD2 36
#define PLD3 68
#define VT_OFF 0
#define Q_OFF  (64 * PLD3)                 // 4352
#define K_OFF  (Q_OFF + 128 * QLD2)        // 8960
#define P_OFF  Q_OFF                       // overlays Q+K
#define PART_OFF (K_OFF + 128 * QLD2)      // 13568 (float units)
#define RSUM_OFF (PART_OFF + 512)          // 14080
#define ATTN_SMEMU (RSUM_OFF + 128)        // 14208 u32 = 56832 B

__global__ __launch_bounds__(512)
void attn_kernel(const __half* __restrict__ qkv,
                 const int* __restrict__ lens,
                 __half* __restrict__ out) {
    const int bh = blockIdx.x;
    const int b  = bh / H_;
    const int h  = bh % H_;
    extern __shared__ uint32_t smu[];
    float*  smf = (float*)smu;
    __half* smx = (__half*)smu;

    const int t    = threadIdx.x;
    const int lane = t & 31;
    const int wid  = t >> 5;
    const int g    = lane >> 2;
    const int tg   = lane & 3;
    const int len  = lens[b];

    for (int i4 = t; i4 < S_ * 8; i4 += 512) {
        const int s  = i4 >> 3;
        const int d8 = i4 & 7;
        const float4* base =
            (const float4*)(qkv + (size_t)(b * S_ + s) * (3 * E_) + h * HD_);
        float4 qv = base[d8];
        float4 kv = base[32 + d8];
        float4 vv = base[64 + d8];
        *(float4*)&smu[Q_OFF + s * QLD2 + d8 * 4] = qv;
        *(float4*)&smu[K_OFF + s * QLD2 + d8 * 4] = kv;
        const __half* vh = (const __half*)&vv;
        const int d0 = d8 * 8;
#pragma unroll
        for (int j = 0; j < 8; j++)
            smx[(d0 + j) * (PLD3 * 2) + s] = vh[j];
    }
    __syncthreads();

    // ---- phase 1: warp tile 32(q) x 32(k), 4x4 warp grid, 4 k16 steps ----
    const int wm = (wid & 3) * 32;
    const int wn = (wid >> 2) * 32;
    float acc[2][4][4];
#pragma unroll
    for (int i = 0; i < 2; i++)
#pragma unroll
        for (int j = 0; j < 4; j++)
#pragma unroll
            for (int r = 0; r < 4; r++) acc[i][j][r] = 0.f;

#pragma unroll
    for (int ks = 0; ks < 4; ks++) {
        const int k2 = ks * 8;
        uint32_t af[2][4], bf[4][2];
#pragma unroll
        for (int mf = 0; mf < 2; mf++) {
            const int row = wm + mf * 16 + g;
            af[mf][0] = smu[Q_OFF + row * QLD2 + k2 + tg];
            af[mf][1] = smu[Q_OFF + (row + 8) * QLD2 + k2 + tg];
            af[mf][2] = smu[Q_OFF + row * QLD2 + k2 + tg + 4];
            af[mf][3] = smu[Q_OFF + (row + 8) * QLD2 + k2 + tg + 4];
        }
#pragma unroll
        for (int nf = 0; nf < 4; nf++) {
            const int col = wn + nf * 8 + g;
            bf[nf][0] = smu[K_OFF + col * QLD2 + k2 + tg];
            bf[nf][1] = smu[K_OFF + col * QLD2 + k2 + tg + 4];
        }
#pragma unroll
        for (int mf = 0; mf < 2; mf++)
#pragma unroll
            for (int nf = 0; nf < 4; nf++) MMA_F16(acc[mf][nf], af[mf], bf[nf]);
    }

    // exp + row partial sums
    float rs[2][2];
#pragma unroll
    for (int mf = 0; mf < 2; mf++) { rs[mf][0] = 0.f; rs[mf][1] = 0.f; }
#pragma unroll
    for (int mf = 0; mf < 2; mf++) {
#pragma unroll
        for (int nf = 0; nf < 4; nf++) {
            const int c0 = wn + nf * 8 + 2 * tg;
            const int c1 = c0 + 1;
            float* d = acc[mf][nf];
            d[0] = (c0 < len) ? __expf(d[0] * 0.125f) : 0.f;
            d[1] = (c1 < len) ? __expf(d[1] * 0.125f) : 0.f;
            d[2] = (c0 < len) ? __expf(d[2] * 0.125f) : 0.f;
            d[3] = (c1 < len) ? __expf(d[3] * 0.125f) : 0.f;
            rs[mf][0] += d[0] + d[1];
            rs[mf][1] += d[2] + d[3];
        }
#pragma unroll
        for (int o = 1; o < 4; o <<= 1) {
            rs[mf][0] += __shfl_xor_sync(0xffffffffu, rs[mf][0], o);
            rs[mf][1] += __shfl_xor_sync(0xffffffffu, rs[mf][1], o);
        }
    }
    __syncthreads();   // Q/K reads done -> overlay P

    const int nidx = wid >> 2;
#pragma unroll
    for (int mf = 0; mf < 2; mf++) {
        const int r0 = wm + mf * 16 + g;
        const int r1 = r0 + 8;
#pragma unroll
        for (int nf = 0; nf < 4; nf++) {
            const int c2 = (wn >> 1) + nf * 4 + tg;   // half2 index of col c0
            const float* d = acc[mf][nf];
            smu[P_OFF + r0 * PLD3 + c2] = f22h2(d[0], d[1]);
            smu[P_OFF + r1 * PLD3 + c2] = f22h2(d[2], d[3]);
        }
        if (tg == 0) {
            smf[PART_OFF + r0 * 4 + nidx] = rs[mf][0];
            smf[PART_OFF + r1 * 4 + nidx] = rs[mf][1];
        }
    }
    __syncthreads();

    if (t < 128) {
        const float s = smf[PART_OFF + t * 4] + smf[PART_OFF + t * 4 + 1] +
                        smf[PART_OFF + t * 4 + 2] + smf[PART_OFF + t * 4 + 3];
        smf[RSUM_OFF + t] = 1.f / s;
    }
    __syncthreads();

    // ---- phase 2: warp tile 16(q) x 32(d), 8x2 warp grid, 8 k16 steps ----
    const int wm2 = (wid & 7) * 16;
    const int wn2 = (wid >> 3) * 32;
    float acc2[4][4];
#pragma unroll
    for (int j = 0; j < 4; j++)
#pragma unroll
        for (int r = 0; r < 4; r++) acc2[j][r] = 0.f;

#pragma unroll
    for (int ks = 0; ks < 8; ks++) {
        const int k2 = ks * 8;
        uint32_t af[4], bf[4][2];
        {
            const int row = wm2 + g;
            af[0] = smu[P_OFF + row * PLD3 + k2 + tg];
            af[1] = smu[P_OFF + (row + 8) * PLD3 + k2 + tg];
            af[2] = smu[P_OFF + row * PLD3 + k2 + tg + 4];
            af[3] = smu[P_OFF + (row + 8) * PLD3 + k2 + tg + 4];
        }
#pragma unroll
        for (int nf = 0; nf < 4; nf++) {
            const int col = wn2 + nf * 8 + g;
            bf[nf][0] = smu[VT_OFF + col * PLD3 + k2 + tg];
            bf[nf][1] = smu[VT_OFF + col * PLD3 + k2 + tg + 4];
        }
#pragma unroll
        for (int nf = 0; nf < 4; nf++) MMA_F16(acc2[nf], af, bf[nf]);
    }

    // normalize + store (half2)
    {
        const int r0 = wm2 + g;
        const int r1 = r0 + 8;
        const float i0 = smf[RSUM_OFF + r0];
        const float i1 = smf[RSUM_OFF + r1];
#pragma unroll
        for (int nf = 0; nf < 4; nf++) {
            const int c = wn2 + nf * 8 + 2 * tg;
            const float* d = acc2[nf];
            *(uint32_t*)(out + (size_t)(b * S_ + r0) * E_ + h * HD_ + c) =
                f22h2(d[0] * i0, d[1] * i0);
            *(uint32_t*)(out + (size_t)(b * S_ + r1) * E_ + h * HD_ + c) =
                f22h2(d[2] * i1, d[3] * i1);
        }
    }
}

// ---------------------------------------------------------------------------
// Fused residual add + LayerNorm (two-input; fp32 residual-sum path):
// warp per token, fp16 in/out, fp32 math.  (R14-proven)
// ---------------------------------------------------------------------------
__global__ __launch_bounds__(256)
void add_ln_kernel(const __half* __restrict__ x, const __half* __restrict__ y,
                   const float* __restrict__ sc, const float* __restrict__ bi,
                   __half* __restrict__ out) {
    const int tok  = blockIdx.x * 8 + (threadIdx.x >> 5);
    const int lane = threadIdx.x & 31;

    uint4 xv = ((const uint4*)(x + (size_t)tok * E_))[lane];
    uint4 yv = ((const uint4*)(y + (size_t)tok * E_))[lane];
    float2 v[4];
    {
        float2 a, c;
        a = h22f2(xv.x); c = h22f2(yv.x); v[0] = make_float2(a.x + c.x, a.y + c.y);
        a = h22f2(xv.y); c = h22f2(yv.y); v[1] = make_float2(a.x + c.x, a.y + c.y);
        a = h22f2(xv.z); c = h22f2(yv.z); v[2] = make_float2(a.x + c.x, a.y + c.y);
        a = h22f2(xv.w); c = h22f2(yv.w); v[3] = make_float2(a.x + c.x, a.y + c.y);
    }
    float s = 0.f;
#pragma unroll
    for (int i = 0; i < 4; i++) s += v[i].x + v[i].y;
#pragma unroll
    for (int o = 16; o; o >>= 1) s += __shfl_xor_sync(0xffffffffu, s, o);
    const float m = s * (1.f / E_);

    float q = 0.f;
#pragma unroll
    for (int i = 0; i < 4; i++) {
        q += (v[i].x - m) * (v[i].x - m) + (v[i].y - m) * (v[i].y - m);
    }
#pragma unroll
    for (int o = 16; o; o >>= 1) q += __shfl_xor_sync(0xffffffffu, q, o);
    const float rstd = rsqrtf(q * (1.f / E_) + 1e-5f);

    const float4 s0 = ((const float4*)sc)[lane * 2];
    const float4 s1 = ((const float4*)sc)[lane * 2 + 1];
    const float4 b0 = ((const float4*)bi)[lane * 2];
    const float4 b1 = ((const float4*)bi)[lane * 2 + 1];
    uint4 o;
    o.x = f22h2((v[0].x - m) * rstd * s0.x + b0.x,
                (v[0].y - m) * rstd * s0.y + b0.y);
    o.y = f22h2((v[1].x - m) * rstd * s0.z + b0.z,
                (v[1].y - m) * rstd * s0.w + b0.w);
    o.z = f22h2((v[2].x - m) * rstd * s1.x + b1.x,
                (v[2].y - m) * rstd * s1.y + b1.y);
    o.w = f22h2((v[3].x - m) * rstd * s1.z + b1.z,
                (v[3].y - m) * rstd * s1.w + b1.w);
    ((uint4*)(out + (size_t)tok * E_))[lane] = o;
}

// ---------------------------------------------------------------------------
// Weighted pool + concat (+ sigmoid gate); x fp16, outv fp32
// ---------------------------------------------------------------------------
__global__ __launch_bounds__(256)
void pool_kernel(const __half* __restrict__ x, const float* __restrict__ attr_tf,
                 const int* __restrict__ lens, const int* __restrict__ lens_user,
                 const float* __restrict__ feat, const float* __restrict__ fW,
                 const float* __restrict__ fb,
                 const int* __restrict__ user_ids, const int* __restrict__ item_ids,
                 const float* __restrict__ user_emb, const float* __restrict__ item_emb,
                 float* __restrict__ out) {
    const int b = blockIdx.x;
    const int e = threadIdx.x;
    __shared__ float w[S_];
    __shared__ float wu_s;
    if (e == 0) {
        float z = fb[0];
#pragma unroll
        for (int i = 0; i < 13; i++) z += feat[b * 13 + i] * fW[i];
        wu_s = 1.f / (1.f + expf(-z));
    }
    __syncthreads();
    if (e < S_) {
        const int s = e;
        float wgt = 0.f;
        if (s < lens[b]) {
            const float g = (s < lens_user[b]) ? wu_s : (1.f - wu_s);
            wgt = attr_tf[b * S_ + s] * g;
        }
        w[s] = wgt;
    }
    __syncthreads();
    float acc = 0.f;
    const __half* xb = x + (size_t)b * S_ * E_ + e;
    for (int s = 0; s < S_; s++) acc += w[s] * __half2float(xb[(size_t)s * E_]);
    out[(size_t)b * 3 * E_ + E_ + e]     = acc;
    out[(size_t)b * 3 * E_ + e]          = user_emb[(size_t)user_ids[b] * E_ + e];
    out[(size_t)b * 3 * E_ + 2 * E_ + e] = item_emb[(size_t)item_ids[b] * E_ + e];
}

// ---------------------------------------------------------------------------
// Scoring head: one warp per PAIR of targets (j, j+300); fp32 throughout
// ---------------------------------------------------------------------------
__global__ __launch_bounds__(256)
void logits_kernel(const float* __restrict__ outv, const float* __restrict__ out_emb,
                   const int* __restrict__ pos_t, const int* __restrict__ pos_l,
                   const int* __restrict__ neg_t, const int* __restrict__ neg_l,
                   float* __restrict__ dout) {
    const int gw   = (int)((blockIdx.x * blockDim.x + threadIdx.x) >> 5);
    const int lane = threadIdx.x & 31;
    if (gw >= B_ * NTH_) return;
    const int b  = gw / NTH_;
    const int j1 = gw % NTH_;
    const int j2 = j1 + NTH_;

    const int pl = pos_l[b];
    const int nl = neg_l[b];

    int tgt1; float valid1, posf1;
    if (j1 < P_) {
        tgt1 = pos_t[b * P_ + j1]; valid1 = (j1 < pl) ? 1.f : 0.f; posf1 = 1.f;
    } else {
        const int jn = j1 - P_;
        tgt1 = neg_t[b * N_ + jn]; valid1 = (jn < nl) ? 1.f : 0.f; posf1 = 0.f;
    }
    int tgt2; float valid2, posf2;
    {
        const int jn = j2 - P_;
        tgt2 = neg_t[b * N_ + jn]; valid2 = (jn < nl) ? 1.f : 0.f; posf2 = 0.f;
    }

    const float4* ovs = (const float4*)(outv + (size_t)b * (3 * E_));
    const float4* e1  = (const float4*)(out_emb + (size_t)tgt1 * (3 * E_));
    const float4* e2  = (const float4*)(out_emb + (size_t)tgt2 * (3 * E_));
    float a1 = 0.f, a2 = 0.f;
#pragma unroll
    for (int i = 0; i < 6; i++) {
        const int k4 = lane + i * 32;
        const float4 c  = ovs[k4];
        const float4 r1 = e1[k4];
        const float4 r2 = e2[k4];
        a1 += r1.x * c.x + r1.y * c.y + r1.z * c.z + r1.w * c.w;
        a2 += r2.x * c.x + r2.y * c.y + r2.z * c.z + r2.w * c.w;
    }
#pragma unroll
    for (int o = 16; o; o >>= 1) {
        a1 += __shfl_xor_sync(0xffffffffu, a1, o);
        a2 += __shfl_xor_sync(0xffffffffu, a2, o);
    }
    if (lane == 0) {
        const int idx1 = b * NT_ + j1;
        const int idx2 = b * NT_ + j2;
        dout[idx1]                = a1;
        dout[B_ * NT_ + idx1]     = valid1;
        dout[2 * B_ * NT_ + idx1] = posf1 * valid1;
        dout[idx2]                = a2;
        dout[B_ * NT_ + idx2]     = valid2;
        dout[2 * B_ * NT_ + idx2] = posf2 * valid2;
    }
}

// ---------------------------------------------------------------------------
// Launch
// ---------------------------------------------------------------------------
extern "C" void kernel_launch(void* const* d_in, const int* in_sizes, int n_in,
                              void* d_out, int out_size) {
    const int*   attr           = (const int*)  d_in[0];
    const float* attr_tf        = (const float*)d_in[2];
    const float* attr_feat      = (const float*)d_in[3];
    const int*   attr_lens      = (const int*)  d_in[4];
    const int*   attr_lens_user = (const int*)  d_in[5];
    const int*   user_ids       = (const int*)  d_in[7];
    const int*   item_ids       = (const int*)  d_in[8];
    const int*   pos_targets    = (const int*)  d_in[9];
    const int*   pos_lens       = (const int*)  d_in[10];
    const int*   neg_targets    = (const int*)  d_in[11];
    const int*   neg_lens       = (const int*)  d_in[12];
    const float* attr_emb       = (const float*)d_in[13];
    const float* user_emb       = (const float*)d_in[14];
    const float* item_emb       = (const float*)d_in[15];
    const float* out_emb        = (const float*)d_in[16];
    const float* fw_W           = (const float*)d_in[17];
    const float* fw_b           = (const float*)d_in[18];
    const float* qkv_w          = (const float*)d_in[19];
    const float* qkv_b          = (const float*)d_in[20];
    const float* attn_out_w     = (const float*)d_in[21];
    const float* attn_out_b     = (const float*)d_in[22];
    const float* ln1_s          = (const float*)d_in[23];
    const float* ln1_b          = (const float*)d_in[24];
    const float* ff1_w          = (const float*)d_in[25];
    const float* ff1_b          = (const float*)d_in[26];
    const float* ff2_w          = (const float*)d_in[27];
    const float* ff2_b          = (const float*)d_in[28];
    const float* ln2_s          = (const float*)d_in[29];
    const float* ln2_b          = (const float*)d_in[30];

    __half *x, *qkv, *attn, *tmp, *ff, *wh;
    float *outv;
    cudaGetSymbolAddress((void**)&x,    g_x);
    cudaGetSymbolAddress((void**)&qkv,  g_qkv);
    cudaGetSymbolAddress((void**)&attn, g_attn);
    cudaGetSymbolAddress((void**)&tmp,  g_tmp);
    cudaGetSymbolAddress((void**)&ff,   g_ff);
    cudaGetSymbolAddress((void**)&outv, g_out);
    cudaGetSymbolAddress((void**)&wh,   g_wh);

    const int gemm_smem = STAGES * 2 * TSZ * (int)sizeof(uint32_t);   // 61440
    cudaFuncSetAttribute(hgemm<false>,
                         cudaFuncAttributeMaxDynamicSharedMemorySize, gemm_smem);
    cudaFuncSetAttribute(hgemm<true>,
                         cudaFuncAttributeMaxDynamicSharedMemorySize, gemm_smem);
    const int attn_smem = ATTN_SMEMU * (int)sizeof(uint32_t);         // 56832
    cudaFuncSetAttribute(attn_kernel, cudaFuncAttributeMaxDynamicSharedMemorySize,
                         attn_smem);

    conv_w_kernel<<<1536, 256>>>((const float4*)qkv_w, (const float4*)attn_out_w,
                                 (const float4*)ff1_w, (const float4*)ff2_w,
                                 (uint32_t*)wh);
    gather_kernel<<<(T_ * E_ / 8 + 255) / 256, 256>>>(attr, attr_emb, x);

    for (int l = 0; l < L_; l++) {
        const __half* lqkv_w = wh + WR_QKV + (size_t)l * 3 * E_ * E_;
        const __half* lao_w  = wh + WR_AO  + (size_t)l * E_ * E_;
        const __half* lf1_w  = wh + WR_FF1 + (size_t)l * F_ * E_;
        const __half* lf2_w  = wh + WR_FF2 + (size_t)l * E_ * F_;
        const float* lqkv_b = qkv_b      + (size_t)l * 3 * E_;
        const float* lao_b  = attn_out_b + (size_t)l * E_;
        const float* l1s    = ln1_s + (size_t)l * E_;
        const float* l1b    = ln1_b + (size_t)l * E_;
        const float* lf1_b  = ff1_b + (size_t)l * F_;
        const float* lf2_b  = ff2_b + (size_t)l * E_;
        const float* l2s    = ln2_s + (size_t)l * E_;
        const float* l2b    = ln2_b + (size_t)l * E_;

        hgemm<false><<<dim3(3 * E_ / 128, T_ / 128), 256, gemm_smem>>>(
            x, lqkv_w, lqkv_b, qkv, T_, 3 * E_, E_);
        attn_kernel<<<B_ * H_, 512, attn_smem>>>(qkv, attr_lens, attn);
        hgemm<false><<<dim3(E_ / 128, T_ / 128), 256, gemm_smem>>>(
            attn, lao_w, lao_b, tmp, T_, E_, E_);
        add_ln_kernel<<<T_ / 8, 256>>>(x, tmp, l1s, l1b, x);
        hgemm<true><<<dim3(F_ / 128, T_ / 128), 256, gemm_smem>>>(
            x, lf1_w, lf1_b, ff, T_, F_, E_);
        hgemm<false><<<dim3(E_ / 128, T_ / 128), 256, gemm_smem>>>(
            ff, lf2_w, lf2_b, tmp, T_, E_, F_);
        add_ln_kernel<<<T_ / 8, 256>>>(x, tmp, l2s, l2b, x);
    }

    pool_kernel<<<B_, 256>>>(x, attr_tf, attr_lens, attr_lens_user,
                             attr_feat, fw_W, fw_b,
                             user_ids, item_ids, user_emb, item_emb, outv);

    const int nwarps = B_ * NTH_;                      // 76800
    logits_kernel<<<(nwarps * 32 + 255) / 256, 256>>>(
        outv, out_emb, pos_targets, pos_lens, neg_targets, neg_lens,
        (float*)d_out);
}

// round 17
// speedup vs baseline: 1.0285x; 1.0114x over previous
#include <cuda_runtime.h>
#include <cuda_fp16.h>
#include <math.h>
#include <stdint.h>

// Problem constants
#define B_   256
#define S_   128
#define P_   100
#define N_   500
#define E_   256
#define H_   4
#define HD_  64
#define L_   2
#define F_   1024
#define T_   (B_ * S_)      // 32768 tokens
#define NT_  (P_ + N_)      // 600 targets
#define NTH_ (NT_ / 2)      // 300 pairs per sample

// ---------------------------------------------------------------------------
// Scratch (device globals — no allocation allowed). Activations in fp16.
// ---------------------------------------------------------------------------
__device__ __half g_x   [(size_t)T_ * E_];
__device__ __half g_qkv [(size_t)T_ * 3 * E_];
__device__ __half g_attn[(size_t)T_ * E_];
__device__ __half g_tmp [(size_t)T_ * E_];
__device__ __half g_ff  [(size_t)T_ * F_];
__device__ float  g_out [(size_t)B_ * 3 * E_];
__device__ __half g_wh  [1572864];            // fp16 weights (3MB)

// half-element offsets into g_wh
#define WR_QKV 0
#define WR_AO  393216
#define WR_FF1 524288
#define WR_FF2 1048576

// ---------------------------------------------------------------------------
// helpers
// ---------------------------------------------------------------------------
__device__ __forceinline__ void cp16(void* sdst, const void* gsrc) {
    uint32_t s = (uint32_t)__cvta_generic_to_shared(sdst);
    asm volatile("cp.async.cg.shared.global [%0], [%1], 16;\n" :: "r"(s), "l"(gsrc));
}
__device__ __forceinline__ void cp_commit() {
    asm volatile("cp.async.commit_group;\n");
}
template<int NWait>
__device__ __forceinline__ void cp_wait() {
    asm volatile("cp.async.wait_group %0;\n" :: "n"(NWait));
}
__device__ __forceinline__ uint32_t f22h2(float a, float b) {
    __half2 h = __floats2half2_rn(a, b);
    return *(uint32_t*)&h;
}
__device__ __forceinline__ float2 h22f2(uint32_t u) {
    return __half22float2(*(__half2*)&u);
}
#define MMA_F16(d, a, b)                                                      \
    asm volatile(                                                             \
        "mma.sync.aligned.m16n8k16.row.col.f32.f16.f16.f32 "                  \
        "{%0,%1,%2,%3}, {%4,%5,%6,%7}, {%8,%9}, {%0,%1,%2,%3};"               \
        : "+f"(d[0]), "+f"(d[1]), "+f"(d[2]), "+f"(d[3])                      \
        : "r"(a[0]), "r"(a[1]), "r"(a[2]), "r"(a[3]), "r"(b[0]), "r"(b[1]))

// ---------------------------------------------------------------------------
// Weight conversion fp32 -> fp16 (once per launch)
// ---------------------------------------------------------------------------
__global__ void conv_w_kernel(const float4* __restrict__ qkvw,
                              const float4* __restrict__ aow,
                              const float4* __restrict__ f1w,
                              const float4* __restrict__ f2w,
                              uint32_t* __restrict__ dst) {
    const int i = blockIdx.x * blockDim.x + threadIdx.x;
    if (i >= 393216) return;
    float4 v;
    int o = i;
    if (o < 98304)                  v = qkvw[o];
    else if ((o -= 98304) < 32768)  v = aow[o];
    else if ((o -= 32768) < 131072) v = f1w[o];
    else                            v = f2w[o - 131072];
    dst[2 * i]     = f22h2(v.x, v.y);
    dst[2 * i + 1] = f22h2(v.z, v.w);
}

// ---------------------------------------------------------------------------
// Embedding gather: fp32 emb -> fp16 x. Thread handles 8 halves.
// ---------------------------------------------------------------------------
__global__ void gather_kernel(const int* __restrict__ attr,
                              const float* __restrict__ emb,
                              __half* __restrict__ x) {
    int i = blockIdx.x * blockDim.x + threadIdx.x;
    if (i < T_ * (E_ / 8)) {
        int t  = i >> 5;
        int e8 = i & 31;
        const float4* src = (const float4*)(emb + (size_t)attr[t] * E_) + e8 * 2;
        float4 v0 = src[0], v1 = src[1];
        uint4 o;
        o.x = f22h2(v0.x, v0.y); o.y = f22h2(v0.z, v0.w);
        o.z = f22h2(v1.x, v1.y); o.w = f22h2(v1.z, v1.w);
        *(uint4*)(x + (size_t)t * E_ + e8 * 8) = o;
    }
}

// ---------------------------------------------------------------------------
// FP16 tensor-core GEMM (R16-proven): BK=32, 8 warps of 64x32, 3-stage
// cp.async, 2 CTAs/SM, LDW=20 conflict-free smem.
// ---------------------------------------------------------------------------
#define LDW    20
#define TSZ    (128 * LDW)     // u32 per matrix per stage
#define STAGES 3

template<bool RELU>
__global__ __launch_bounds__(256, 2)
void hgemm(const __half* __restrict__ A, const __half* __restrict__ Bm,
           const float* __restrict__ bias, __half* __restrict__ C,
           int M, int N, int K) {
    extern __shared__ uint32_t smh[];
    uint32_t* As = smh;
    uint32_t* Bs = smh + STAGES * TSZ;

    const int bm   = blockIdx.y * 128;
    const int bn   = blockIdx.x * 128;
    const int t    = threadIdx.x;
    const int lane = t & 31;
    const int wid  = t >> 5;
    const int wm   = (wid & 1) * 64;
    const int wn   = (wid >> 1) * 32;
    const int g    = lane >> 2;
    const int tg   = lane & 3;

    const int lrow = t >> 1;            // 0..127
    const int lk   = (t & 1);           // which 16-half chunk
    const __half* Ap = A  + (size_t)(bm + lrow) * K + lk * 16;
    const __half* Bp = Bm + (size_t)(bn + lrow) * K + lk * 16;

    float acc[4][4][4];
#pragma unroll
    for (int i = 0; i < 4; i++)
#pragma unroll
        for (int j = 0; j < 4; j++)
#pragma unroll
            for (int r = 0; r < 4; r++) acc[i][j][r] = 0.f;

    const int nk = K >> 5;
#pragma unroll
    for (int s = 0; s < STAGES - 1; s++) {
        const int k0 = s << 5;
        cp16(&As[s * TSZ + lrow * LDW + lk * 8],     Ap + k0);
        cp16(&As[s * TSZ + lrow * LDW + lk * 8 + 4], Ap + k0 + 8);
        cp16(&Bs[s * TSZ + lrow * LDW + lk * 8],     Bp + k0);
        cp16(&Bs[s * TSZ + lrow * LDW + lk * 8 + 4], Bp + k0 + 8);
        cp_commit();
    }

    int cur = 0;
    for (int kt = 0; kt < nk; kt++) {
        if (kt < nk - 1) cp_wait<STAGES - 2>(); else cp_wait<0>();
        __syncthreads();

        const uint32_t* Ac = As + cur * TSZ;
        const uint32_t* Bc = Bs + cur * TSZ;
#pragma unroll
        for (int ks = 0; ks < 2; ks++) {
            const int k2 = ks * 8;
            uint32_t af[4][4], bf[4][2];
#pragma unroll
            for (int mf = 0; mf < 4; mf++) {
                const int row = wm + mf * 16 + g;
                af[mf][0] = Ac[row * LDW + k2 + tg];
                af[mf][1] = Ac[(row + 8) * LDW + k2 + tg];
                af[mf][2] = Ac[row * LDW + k2 + tg + 4];
                af[mf][3] = Ac[(row + 8) * LDW + k2 + tg + 4];
            }
#pragma unroll
            for (int nf = 0; nf < 4; nf++) {
                const int col = wn + nf * 8 + g;
                bf[nf][0] = Bc[col * LDW + k2 + tg];
                bf[nf][1] = Bc[col * LDW + k2 + tg + 4];
            }
#pragma unroll
            for (int mf = 0; mf < 4; mf++)
#pragma unroll
                for (int nf = 0; nf < 4; nf++) MMA_F16(acc[mf][nf], af[mf], bf[nf]);
        }

        const int pf = kt + STAGES - 1;
        if (pf < nk) {
            const int ps = pf % STAGES;
            const int k0 = pf << 5;
            cp16(&As[ps * TSZ + lrow * LDW + lk * 8],     Ap + k0);
            cp16(&As[ps * TSZ + lrow * LDW + lk * 8 + 4], Ap + k0 + 8);
            cp16(&Bs[ps * TSZ + lrow * LDW + lk * 8],     Bp + k0);
            cp16(&Bs[ps * TSZ + lrow * LDW + lk * 8 + 4], Bp + k0 + 8);
            cp_commit();
        }
        cur = (cur + 1 == STAGES) ? 0 : cur + 1;
    }

    // epilogue: bias (+ReLU), half2 stores
#pragma unroll
    for (int nf = 0; nf < 4; nf++) {
        const int col = bn + wn + nf * 8 + 2 * tg;
        const float b0v = bias[col], b1v = bias[col + 1];
#pragma unroll
        for (int mf = 0; mf < 4; mf++) {
            const int row = bm + wm + mf * 16 + g;
            float v0 = acc[mf][nf][0] + b0v;
            float v1 = acc[mf][nf][1] + b1v;
            float v2 = acc[mf][nf][2] + b0v;
            float v3 = acc[mf][nf][3] + b1v;
            if (RELU) {
                v0 = fmaxf(v0, 0.f); v1 = fmaxf(v1, 0.f);
                v2 = fmaxf(v2, 0.f); v3 = fmaxf(v3, 0.f);
            }
            *(uint32_t*)(C + (size_t)row * N + col)       = f22h2(v0, v1);
            *(uint32_t*)(C + (size_t)(row + 8) * N + col) = f22h2(v2, v3);
        }
    }
}

// ---------------------------------------------------------------------------
// FP16 tensor-core attention: one block per (b,h), 512 threads (16 warps).
// V transposed into Vt via half2 (row-pair) stores with XOR swizzle
// w' = w ^ (4*(d>>3))  -> conflict-free stores AND loads (swizzle constant
// per fragment). Q/K layout and both MMA phases otherwise as R16.
// ---------------------------------------------------------------------------
#define QLD2 36
#define PLD3 68
#define VT_OFF 0
#define Q_OFF  (64 * PLD3)                 // 4352
#define K_OFF  (Q_OFF + 128 * QLD2)        // 8960
#define P_OFF  Q_OFF                       // overlays Q+K
#define PART_OFF (K_OFF + 128 * QLD2)      // 13568 (float units)
#define RSUM_OFF (PART_OFF + 512)          // 14080
#define ATTN_SMEMU (RSUM_OFF + 128)        // 14208 u32 = 56832 B

__global__ __launch_bounds__(512)
void attn_kernel(const __half* __restrict__ qkv,
                 const int* __restrict__ lens,
                 __half* __restrict__ out) {
    const int bh = blockIdx.x;
    const int b  = bh / H_;
    const int h  = bh % H_;
    extern __shared__ uint32_t smu[];
    float* smf = (float*)smu;

    const int t    = threadIdx.x;
    const int lane = t & 31;
    const int wid  = t >> 5;
    const int g    = lane >> 2;
    const int tg   = lane & 3;
    const int len  = lens[b];

    // Q/K rows (float4 = 8 halves per chunk); 1024 items over 512 threads
    for (int i4 = t; i4 < S_ * 8; i4 += 512) {
        const int s  = i4 >> 3;
        const int d8 = i4 & 7;
        const float4* base =
            (const float4*)(qkv + (size_t)(b * S_ + s) * (3 * E_) + h * HD_);
        *(float4*)&smu[Q_OFF + s * QLD2 + d8 * 4] = base[d8];
        *(float4*)&smu[K_OFF + s * QLD2 + d8 * 4] = base[32 + d8];
    }
    // V transpose: thread t handles row-pair p = t>>3 (rows 2p,2p+1), chunk
    // d8 = t&7. Emits 8 half2 stores Vt[d][p] at u32 index d*PLD3 + (p ^ 4*d8)
    // -> all 32 lanes hit distinct banks for each j.
    {
        const int p  = t >> 3;             // 0..63
        const int d8 = t & 7;
        const float4* b0 =
            (const float4*)(qkv + (size_t)(b * S_ + 2 * p)     * (3 * E_) + h * HD_);
        const float4* b1 =
            (const float4*)(qkv + (size_t)(b * S_ + 2 * p + 1) * (3 * E_) + h * HD_);
        float4 va = b0[64 + d8];
        float4 vb = b1[64 + d8];
        const __half* ah = (const __half*)&va;
        const __half* bh2 = (const __half*)&vb;
        const int wsw = p ^ (d8 << 2);
#pragma unroll
        for (int j = 0; j < 8; j++) {
            __half2 pr = __halves2half2(ah[j], bh2[j]);
            smu[VT_OFF + (d8 * 8 + j) * PLD3 + wsw] = *(uint32_t*)&pr;
        }
    }
    __syncthreads();

    // ---- phase 1: warp tile 32(q) x 32(k), 4x4 warp grid, 4 k16 steps ----
    const int wm = (wid & 3) * 32;
    const int wn = (wid >> 2) * 32;
    float acc[2][4][4];
#pragma unroll
    for (int i = 0; i < 2; i++)
#pragma unroll
        for (int j = 0; j < 4; j++)
#pragma unroll
            for (int r = 0; r < 4; r++) acc[i][j][r] = 0.f;

#pragma unroll
    for (int ks = 0; ks < 4; ks++) {
        const int k2 = ks * 8;
        uint32_t af[2][4], bf[4][2];
#pragma unroll
        for (int mf = 0; mf < 2; mf++) {
            const int row = wm + mf * 16 + g;
            af[mf][0] = smu[Q_OFF + row * QLD2 + k2 + tg];
            af[mf][1] = smu[Q_OFF + (row + 8) * QLD2 + k2 + tg];
            af[mf][2] = smu[Q_OFF + row * QLD2 + k2 + tg + 4];
            af[mf][3] = smu[Q_OFF + (row + 8) * QLD2 + k2 + tg + 4];
        }
#pragma unroll
        for (int nf = 0; nf < 4; nf++) {
            const int col = wn + nf * 8 + g;
            bf[nf][0] = smu[K_OFF + col * QLD2 + k2 + tg];
            bf[nf][1] = smu[K_OFF + col * QLD2 + k2 + tg + 4];
        }
#pragma unroll
        for (int mf = 0; mf < 2; mf++)
#pragma unroll
            for (int nf = 0; nf < 4; nf++) MMA_F16(acc[mf][nf], af[mf], bf[nf]);
    }

    // exp + row partial sums
    float rs[2][2];
#pragma unroll
    for (int mf = 0; mf < 2; mf++) { rs[mf][0] = 0.f; rs[mf][1] = 0.f; }
#pragma unroll
    for (int mf = 0; mf < 2; mf++) {
#pragma unroll
        for (int nf = 0; nf < 4; nf++) {
            const int c0 = wn + nf * 8 + 2 * tg;
            const int c1 = c0 + 1;
            float* d = acc[mf][nf];
            d[0] = (c0 < len) ? __expf(d[0] * 0.125f) : 0.f;
            d[1] = (c1 < len) ? __expf(d[1] * 0.125f) : 0.f;
            d[2] = (c0 < len) ? __expf(d[2] * 0.125f) : 0.f;
            d[3] = (c1 < len) ? __expf(d[3] * 0.125f) : 0.f;
            rs[mf][0] += d[0] + d[1];
            rs[mf][1] += d[2] + d[3];
        }
#pragma unroll
        for (int o = 1; o < 4; o <<= 1) {
            rs[mf][0] += __shfl_xor_sync(0xffffffffu, rs[mf][0], o);
            rs[mf][1] += __shfl_xor_sync(0xffffffffu, rs[mf][1], o);
        }
    }
    __syncthreads();   // Q/K reads done -> overlay P

    const int nidx = wid >> 2;
#pragma unroll
    for (int mf = 0; mf < 2; mf++) {
        const int r0 = wm + mf * 16 + g;
        const int r1 = r0 + 8;
#pragma unroll
        for (int nf = 0; nf < 4; nf++) {
            const int c2 = (wn >> 1) + nf * 4 + tg;   // half2 index of col c0
            const float* d = acc[mf][nf];
            smu[P_OFF + r0 * PLD3 + c2] = f22h2(d[0], d[1]);
            smu[P_OFF + r1 * PLD3 + c2] = f22h2(d[2], d[3]);
        }
        if (tg == 0) {
            smf[PART_OFF + r0 * 4 + nidx] = rs[mf][0];
            smf[PART_OFF + r1 * 4 + nidx] = rs[mf][1];
        }
    }
    __syncthreads();

    if (t < 128) {
        const float s = smf[PART_OFF + t * 4] + smf[PART_OFF + t * 4 + 1] +
                        smf[PART_OFF + t * 4 + 2] + smf[PART_OFF + t * 4 + 3];
        smf[RSUM_OFF + t] = 1.f / s;
    }
    __syncthreads();

    // ---- phase 2: warp tile 16(q) x 32(d), 8x2 warp grid, 8 k16 steps ----
    const int wm2 = (wid & 7) * 16;
    const int wn2 = (wid >> 3) * 32;
    float acc2[4][4];
#pragma unroll
    for (int j = 0; j < 4; j++)
#pragma unroll
        for (int r = 0; r < 4; r++) acc2[j][r] = 0.f;

#pragma unroll
    for (int ks = 0; ks < 8; ks++) {
        const int k2 = ks * 8;
        uint32_t af[4], bf[4][2];
        {
            const int row = wm2 + g;
            af[0] = smu[P_OFF + row * PLD3 + k2 + tg];
            af[1] = smu[P_OFF + (row + 8) * PLD3 + k2 + tg];
            af[2] = smu[P_OFF + row * PLD3 + k2 + tg + 4];
            af[3] = smu[P_OFF + (row + 8) * PLD3 + k2 + tg + 4];
        }
#pragma unroll
        for (int nf = 0; nf < 4; nf++) {
            const int col = wn2 + nf * 8 + g;
            const int swz = ((col >> 3) << 2);      // constant per fragment
            bf[nf][0] = smu[VT_OFF + col * PLD3 + ((k2 + tg) ^ swz)];
            bf[nf][1] = smu[VT_OFF + col * PLD3 + ((k2 + tg + 4) ^ swz)];
        }
#pragma unroll
        for (int nf = 0; nf < 4; nf++) MMA_F16(acc2[nf], af, bf[nf]);
    }

    // normalize + store (half2)
    {
        const int r0 = wm2 + g;
        const int r1 = r0 + 8;
        const float i0 = smf[RSUM_OFF + r0];
        const float i1 = smf[RSUM_OFF + r1];
#pragma unroll
        for (int nf = 0; nf < 4; nf++) {
            const int c = wn2 + nf * 8 + 2 * tg;
            const float* d = acc2[nf];
            *(uint32_t*)(out + (size_t)(b * S_ + r0) * E_ + h * HD_ + c) =
                f22h2(d[0] * i0, d[1] * i0);
            *(uint32_t*)(out + (size_t)(b * S_ + r1) * E_ + h * HD_ + c) =
                f22h2(d[2] * i1, d[3] * i1);
        }
    }
}

// ---------------------------------------------------------------------------
// Fused residual add + LayerNorm (two-input; fp32 residual-sum path)
// ---------------------------------------------------------------------------
__global__ __launch_bounds__(256)
void add_ln_kernel(const __half* __restrict__ x, const __half* __restrict__ y,
                   const float* __restrict__ sc, const float* __restrict__ bi,
                   __half* __restrict__ out) {
    const int tok  = blockIdx.x * 8 + (threadIdx.x >> 5);
    const int lane = threadIdx.x & 31;

    uint4 xv = ((const uint4*)(x + (size_t)tok * E_))[lane];
    uint4 yv = ((const uint4*)(y + (size_t)tok * E_))[lane];
    float2 v[4];
    {
        float2 a, c;
        a = h22f2(xv.x); c = h22f2(yv.x); v[0] = make_float2(a.x + c.x, a.y + c.y);
        a = h22f2(xv.y); c = h22f2(yv.y); v[1] = make_float2(a.x + c.x, a.y + c.y);
        a = h22f2(xv.z); c = h22f2(yv.z); v[2] = make_float2(a.x + c.x, a.y + c.y);
        a = h22f2(xv.w); c = h22f2(yv.w); v[3] = make_float2(a.x + c.x, a.y + c.y);
    }
    float s = 0.f;
#pragma unroll
    for (int i = 0; i < 4; i++) s += v[i].x + v[i].y;
#pragma unroll
    for (int o = 16; o; o >>= 1) s += __shfl_xor_sync(0xffffffffu, s, o);
    const float m = s * (1.f / E_);

    float q = 0.f;
#pragma unroll
    for (int i = 0; i < 4; i++) {
        q += (v[i].x - m) * (v[i].x - m) + (v[i].y - m) * (v[i].y - m);
    }
#pragma unroll
    for (int o = 16; o; o >>= 1) q += __shfl_xor_sync(0xffffffffu, q, o);
    const float rstd = rsqrtf(q * (1.f / E_) + 1e-5f);

    const float4 s0 = ((const float4*)sc)[lane * 2];
    const float4 s1 = ((const float4*)sc)[lane * 2 + 1];
    const float4 b0 = ((const float4*)bi)[lane * 2];
    const float4 b1 = ((const float4*)bi)[lane * 2 + 1];
    uint4 o;
    o.x = f22h2((v[0].x - m) * rstd * s0.x + b0.x,
                (v[0].y - m) * rstd * s0.y + b0.y);
    o.y = f22h2((v[1].x - m) * rstd * s0.z + b0.z,
                (v[1].y - m) * rstd * s0.w + b0.w);
    o.z = f22h2((v[2].x - m) * rstd * s1.x + b1.x,
                (v[2].y - m) * rstd * s1.y + b1.y);
    o.w = f22h2((v[3].x - m) * rstd * s1.z + b1.z,
                (v[3].y - m) * rstd * s1.w + b1.w);
    ((uint4*)(out + (size_t)tok * E_))[lane] = o;
}

// ---------------------------------------------------------------------------
// Weighted pool + concat (+ sigmoid gate); x fp16, outv fp32
// ---------------------------------------------------------------------------
__global__ __launch_bounds__(256)
void pool_kernel(const __half* __restrict__ x, const float* __restrict__ attr_tf,
                 const int* __restrict__ lens, const int* __restrict__ lens_user,
                 const float* __restrict__ feat, const float* __restrict__ fW,
                 const float* __restrict__ fb,
                 const int* __restrict__ user_ids, const int* __restrict__ item_ids,
                 const float* __restrict__ user_emb, const float* __restrict__ item_emb,
                 float* __restrict__ out) {
    const int b = blockIdx.x;
    const int e = threadIdx.x;
    __shared__ float w[S_];
    __shared__ float wu_s;
    if (e == 0) {
        float z = fb[0];
#pragma unroll
        for (int i = 0; i < 13; i++) z += feat[b * 13 + i] * fW[i];
        wu_s = 1.f / (1.f + expf(-z));
    }
    __syncthreads();
    if (e < S_) {
        const int s = e;
        float wgt = 0.f;
        if (s < lens[b]) {
            const float g = (s < lens_user[b]) ? wu_s : (1.f - wu_s);
            wgt = attr_tf[b * S_ + s] * g;
        }
        w[s] = wgt;
    }
    __syncthreads();
    float acc = 0.f;
    const __half* xb = x + (size_t)b * S_ * E_ + e;
    for (int s = 0; s < S_; s++) acc += w[s] * __half2float(xb[(size_t)s * E_]);
    out[(size_t)b * 3 * E_ + E_ + e]     = acc;
    out[(size_t)b * 3 * E_ + e]          = user_emb[(size_t)user_ids[b] * E_ + e];
    out[(size_t)b * 3 * E_ + 2 * E_ + e] = item_emb[(size_t)item_ids[b] * E_ + e];
}

// ---------------------------------------------------------------------------
// Scoring head: one warp per PAIR of targets (j, j+300); fp32 throughout
// ---------------------------------------------------------------------------
__global__ __launch_bounds__(256)
void logits_kernel(const float* __restrict__ outv, const float* __restrict__ out_emb,
                   const int* __restrict__ pos_t, const int* __restrict__ pos_l,
                   const int* __restrict__ neg_t, const int* __restrict__ neg_l,
                   float* __restrict__ dout) {
    const int gw   = (int)((blockIdx.x * blockDim.x + threadIdx.x) >> 5);
    const int lane = threadIdx.x & 31;
    if (gw >= B_ * NTH_) return;
    const int b  = gw / NTH_;
    const int j1 = gw % NTH_;
    const int j2 = j1 + NTH_;

    const int pl = pos_l[b];
    const int nl = neg_l[b];

    int tgt1; float valid1, posf1;
    if (j1 < P_) {
        tgt1 = pos_t[b * P_ + j1]; valid1 = (j1 < pl) ? 1.f : 0.f; posf1 = 1.f;
    } else {
        const int jn = j1 - P_;
        tgt1 = neg_t[b * N_ + jn]; valid1 = (jn < nl) ? 1.f : 0.f; posf1 = 0.f;
    }
    int tgt2; float valid2, posf2;
    {
        const int jn = j2 - P_;
        tgt2 = neg_t[b * N_ + jn]; valid2 = (jn < nl) ? 1.f : 0.f; posf2 = 0.f;
    }

    const float4* ovs = (const float4*)(outv + (size_t)b * (3 * E_));
    const float4* e1  = (const float4*)(out_emb + (size_t)tgt1 * (3 * E_));
    const float4* e2  = (const float4*)(out_emb + (size_t)tgt2 * (3 * E_));
    float a1 = 0.f, a2 = 0.f;
#pragma unroll
    for (int i = 0; i < 6; i++) {
        const int k4 = lane + i * 32;
        const float4 c  = ovs[k4];
        const float4 r1 = e1[k4];
        const float4 r2 = e2[k4];
        a1 += r1.x * c.x + r1.y * c.y + r1.z * c.z + r1.w * c.w;
        a2 += r2.x * c.x + r2.y * c.y + r2.z * c.z + r2.w * c.w;
    }
#pragma unroll
    for (int o = 16; o; o >>= 1) {
        a1 += __shfl_xor_sync(0xffffffffu, a1, o);
        a2 += __shfl_xor_sync(0xffffffffu, a2, o);
    }
    if (lane == 0) {
        const int idx1 = b * NT_ + j1;
        const int idx2 = b * NT_ + j2;
        dout[idx1]                = a1;
        dout[B_ * NT_ + idx1]     = valid1;
        dout[2 * B_ * NT_ + idx1] = posf1 * valid1;
        dout[idx2]                = a2;
        dout[B_ * NT_ + idx2]     = valid2;
        dout[2 * B_ * NT_ + idx2] = posf2 * valid2;
    }
}

// ---------------------------------------------------------------------------
// Launch
// ---------------------------------------------------------------------------
extern "C" void kernel_launch(void* const* d_in, const int* in_sizes, int n_in,
                              void* d_out, int out_size) {
    const int*   attr           = (const int*)  d_in[0];
    const float* attr_tf        = (const float*)d_in[2];
    const float* attr_feat      = (const float*)d_in[3];
    const int*   attr_lens      = (const int*)  d_in[4];
    const int*   attr_lens_user = (const int*)  d_in[5];
    const int*   user_ids       = (const int*)  d_in[7];
    const int*   item_ids       = (const int*)  d_in[8];
    const int*   pos_targets    = (const int*)  d_in[9];
    const int*   pos_lens       = (const int*)  d_in[10];
    const int*   neg_targets    = (const int*)  d_in[11];
    const int*   neg_lens       = (const int*)  d_in[12];
    const float* attr_emb       = (const float*)d_in[13];
    const float* user_emb       = (const float*)d_in[14];
    const float* item_emb       = (const float*)d_in[15];
    const float* out_emb        = (const float*)d_in[16];
    const float* fw_W           = (const float*)d_in[17];
    const float* fw_b           = (const float*)d_in[18];
    const float* qkv_w          = (const float*)d_in[19];
    const float* qkv_b          = (const float*)d_in[20];
    const float* attn_out_w     = (const float*)d_in[21];
    const float* attn_out_b     = (const float*)d_in[22];
    const float* ln1_s          = (const float*)d_in[23];
    const float* ln1_b          = (const float*)d_in[24];
    const float* ff1_w          = (const float*)d_in[25];
    const float* ff1_b          = (const float*)d_in[26];
    const float* ff2_w          = (const float*)d_in[27];
    const float* ff2_b          = (const float*)d_in[28];
    const float* ln2_s          = (const float*)d_in[29];
    const float* ln2_b          = (const float*)d_in[30];

    __half *x, *qkv, *attn, *tmp, *ff, *wh;
    float *outv;
    cudaGetSymbolAddress((void**)&x,    g_x);
    cudaGetSymbolAddress((void**)&qkv,  g_qkv);
    cudaGetSymbolAddress((void**)&attn, g_attn);
    cudaGetSymbolAddress((void**)&tmp,  g_tmp);
    cudaGetSymbolAddress((void**)&ff,   g_ff);
    cudaGetSymbolAddress((void**)&outv, g_out);
    cudaGetSymbolAddress((void**)&wh,   g_wh);

    const int gemm_smem = STAGES * 2 * TSZ * (int)sizeof(uint32_t);   // 61440
    cudaFuncSetAttribute(hgemm<false>,
                         cudaFuncAttributeMaxDynamicSharedMemorySize, gemm_smem);
    cudaFuncSetAttribute(hgemm<true>,
                         cudaFuncAttributeMaxDynamicSharedMemorySize, gemm_smem);
    const int attn_smem = ATTN_SMEMU * (int)sizeof(uint32_t);         // 56832
    cudaFuncSetAttribute(attn_kernel, cudaFuncAttributeMaxDynamicSharedMemorySize,
                         attn_smem);

    conv_w_kernel<<<1536, 256>>>((const float4*)qkv_w, (const float4*)attn_out_w,
                                 (const float4*)ff1_w, (const float4*)ff2_w,
                                 (uint32_t*)wh);
    gather_kernel<<<(T_ * E_ / 8 + 255) / 256, 256>>>(attr, attr_emb, x);

    for (int l = 0; l < L_; l++) {
        const __half* lqkv_w = wh + WR_QKV + (size_t)l * 3 * E_ * E_;
        const __half* lao_w  = wh + WR_AO  + (size_t)l * E_ * E_;
        const __half* lf1_w  = wh + WR_FF1 + (size_t)l * F_ * E_;
        const __half* lf2_w  = wh + WR_FF2 + (size_t)l * E_ * F_;
        const float* lqkv_b = qkv_b      + (size_t)l * 3 * E_;
        const float* lao_b  = attn_out_b + (size_t)l * E_;
        const float* l1s    = ln1_s + (size_t)l * E_;
        const float* l1b    = ln1_b + (size_t)l * E_;
        const float* lf1_b  = ff1_b + (size_t)l * F_;
        const float* lf2_b  = ff2_b + (size_t)l * E_;
        const float* l2s    = ln2_s + (size_t)l * E_;
        const float* l2b    = ln2_b + (size_t)l * E_;

        hgemm<false><<<dim3(3 * E_ / 128, T_ / 128), 256, gemm_smem>>>(
            x, lqkv_w, lqkv_b, qkv, T_, 3 * E_, E_);
        attn_kernel<<<B_ * H_, 512, attn_smem>>>(qkv, attr_lens, attn);
        hgemm<false><<<dim3(E_ / 128, T_ / 128), 256, gemm_smem>>>(
            attn, lao_w, lao_b, tmp, T_, E_, E_);
        add_ln_kernel<<<T_ / 8, 256>>>(x, tmp, l1s, l1b, x);
        hgemm<true><<<dim3(F_ / 128, T_ / 128), 256, gemm_smem>>>(
            x, lf1_w, lf1_b, ff, T_, F_, E_);
        hgemm<false><<<dim3(E_ / 128, T_ / 128), 256, gemm_smem>>>(
            ff, lf2_w, lf2_b, tmp, T_, E_, F_);
        add_ln_kernel<<<T_ / 8, 256>>>(x, tmp, l2s, l2b, x);
    }

    pool_kernel<<<B_, 256>>>(x, attr_tf, attr_lens, attr_lens_user,
                             attr_feat, fw_W, fw_b,
                             user_ids, item_ids, user_emb, item_emb, outv);

    const int nwarps = B_ * NTH_;                      // 76800
    logits_kernel<<<(nwarps * 32 + 255) / 256, 256>>>(
        outv, out_emb, pos_targets, pos_lens, neg_targets, neg_lens,
        (float*)d_out);
}